// round 7
// baseline (speedup 1.0000x reference)
#include <cuda_runtime.h>
#include <math.h>

#define BB 2
#define HH 16
#define DD 64
#define CC 1024
#define TEXT_N 226
#define NTOK_N 1024
#define TOK_N 4096
#define SQ (TEXT_N + NTOK_N)   /* 1250 */
#define SKV (TEXT_N + TOK_N)   /* 4322 */
#define N3C (3*CC)             /* 3072 */
#define SQP 1280
#define SKVP 4352
#define NKT 68                 /* SKVP/64 kv tiles */
#define KSPLIT 34
#define NQT 10
#define MM (BB * SQ)           /* 2500 */

// pairing perm along a k-row of columns: pos(d) groups (d, d+4) adjacent
#define POSD(d) (((d) & ~7) | (((d) & 3) << 1) | (((d) >> 2) & 1))

// ---------------- scratch (zero-initialized at module load) ----------------
__device__ float g_h     [MM * CC];               // rounded, col-paired
__device__ float g_wqkv  [CC * N3C];              // rounded, row-paired [512][2*N3C]
__device__ float g_wo    [CC * CC];               // rounded, row-paired [512][2*CC]
__device__ float g_qkv   [MM * N3C];
__device__ float g_khead [BB * HH * SKVP * DD];   // rounded, col-paired rows
__device__ float g_vhead [BB * HH * SKVP * DD];   // rounded, [bh][tile][unit32][128]
__device__ float g_qhead [BB * HH * SQP * DD];    // rounded*0.125, natural
__device__ float g_attn  [MM * CC];               // rounded, col-paired
__device__ int   g_inv   [TOK_N];
__device__ float g_ml    [2 * 32 * NQT * 128 * 2];
__device__ float g_op    [2 * 32 * NQT * 128 * 64];

// ---------------- helpers ----------------
__device__ __forceinline__ unsigned f2tf(float x) {
    unsigned r;
    asm("cvt.rna.tf32.f32 %0, %1;" : "=r"(r) : "f"(x));
    return r;
}
__device__ __forceinline__ float f2tff(float x) {
    return __uint_as_float(f2tf(x));
}
__device__ __forceinline__ void mma_tf32(float* c, const unsigned* a,
                                         unsigned b0, unsigned b1) {
    asm volatile(
        "mma.sync.aligned.m16n8k8.row.col.f32.tf32.tf32.f32 "
        "{%0,%1,%2,%3}, {%4,%5,%6,%7}, {%8,%9}, {%0,%1,%2,%3};"
        : "+f"(c[0]), "+f"(c[1]), "+f"(c[2]), "+f"(c[3])
        : "r"(a[0]), "r"(a[1]), "r"(a[2]), "r"(a[3]), "r"(b0), "r"(b1));
}
__device__ __forceinline__ void cp16(void* smem_dst, const void* gsrc) {
    unsigned sa = (unsigned)__cvta_generic_to_shared(smem_dst);
    asm volatile("cp.async.cg.shared.global [%0], [%1], 16;" :: "r"(sa), "l"(gsrc));
}
__device__ __forceinline__ void cp16z(void* smem_dst, const void* gsrc, bool pred) {
    unsigned sa = (unsigned)__cvta_generic_to_shared(smem_dst);
    int sz = pred ? 16 : 0;
    asm volatile("cp.async.cg.shared.global [%0], [%1], 16, %2;"
                 :: "r"(sa), "l"(gsrc), "r"(sz));
}
#define CP_COMMIT() asm volatile("cp.async.commit_group;")
#define CP_WAIT1()  asm volatile("cp.async.wait_group 1;")

// ---------------- inverse token map ----------------
__global__ void inv_init_kernel() {
    int i = blockIdx.x * blockDim.x + threadIdx.x;
    if (i < TOK_N) g_inv[i] = -1;
}
__global__ void inv_scatter_kernel(const int* __restrict__ tok) {
    int i = blockIdx.x * blockDim.x + threadIdx.x;
    if (i < NTOK_N) atomicMax(&g_inv[tok[i]], i);
}

// ---------------- prep: rounded + paired copies ----------------
#define PT1 (MM * CC / 4)
#define PT2 (PT1 + CC * N3C / 4)
#define PT3 (PT2 + CC * CC / 4)
__global__ void prep_kernel(const float* __restrict__ hid,
                            const float* __restrict__ enc,
                            const float* __restrict__ Wq,
                            const float* __restrict__ Wk,
                            const float* __restrict__ Wv,
                            const float* __restrict__ Wo) {
    int i = blockIdx.x * blockDim.x + threadIdx.x;
    if (i < PT1) {
        int r = i / (CC / 4), c4 = (i % (CC / 4)) * 4;
        int b = r / SQ, s = r % SQ;
        const float* src = (s < TEXT_N)
            ? enc + ((size_t)b * TEXT_N + s) * CC + c4
            : hid + ((size_t)b * NTOK_N + (s - TEXT_N)) * CC + c4;
        float4 v = *(const float4*)src;
        float* dst = g_h + (size_t)r * CC;
        dst[POSD(c4+0)] = f2tff(v.x);
        dst[POSD(c4+1)] = f2tff(v.y);
        dst[POSD(c4+2)] = f2tff(v.z);
        dst[POSD(c4+3)] = f2tff(v.w);
    } else if (i < PT2) {
        int j = i - PT1;
        int k = j / (N3C / 4);
        int n = (j % (N3C / 4)) * 4;
        const float* src = (n < CC)   ? (Wq + (size_t)k * CC + n)
                         : (n < 2*CC) ? (Wk + (size_t)k * CC + (n - CC))
                                      : (Wv + (size_t)k * CC + (n - 2*CC));
        float4 v = *(const float4*)src;
        int u = ((k >> 3) << 2) | (k & 3);
        int half = (k >> 2) & 1;
        float* dst = g_wqkv + (size_t)u * (2 * N3C) + 2 * n + half;
        dst[0] = f2tff(v.x); dst[2] = f2tff(v.y);
        dst[4] = f2tff(v.z); dst[6] = f2tff(v.w);
    } else if (i < PT3) {
        int j = i - PT2;
        int k = j / (CC / 4);
        int n = (j % (CC / 4)) * 4;
        float4 v = *(const float4*)(Wo + (size_t)k * CC + n);
        int u = ((k >> 3) << 2) | (k & 3);
        int half = (k >> 2) & 1;
        float* dst = g_wo + (size_t)u * (2 * CC) + 2 * n + half;
        dst[0] = f2tff(v.x); dst[2] = f2tff(v.y);
        dst[4] = f2tff(v.z); dst[6] = f2tff(v.w);
    }
}

// ---------------- GEMMs: 128x128 block, K-tile 32, paired frags ----------------
#define ASTR2 40
#define BSTR2 264
#define GEMM_SMEM ((2*128*ASTR2 + 2*16*BSTR2) * 4)   /* 74752 B */

__global__ __launch_bounds__(256) void gemm_qkv_mma() {
    extern __shared__ float smg[];
    float* As = smg;
    float* Bs = smg + 2 * 128 * ASTR2;
    const int tid = threadIdx.x;
    const int lane = tid & 31, wid = tid >> 5;
    const int g = lane >> 2, tig = lane & 3;
    const int wm = wid & 3, wn = wid >> 2;
    const int m0 = blockIdx.y * 128;
    const int n0 = blockIdx.x * 128;

    int ar[4], ac[4]; bool av[4];
#pragma unroll
    for (int k = 0; k < 4; k++) {
        int i = tid + 256 * k;
        ar[k] = i >> 3; ac[k] = (i & 7) << 2;
        av[k] = (m0 + ar[k]) < MM;
    }

    auto stage = [&](int kk, int st) {
        float* dA = As + st * 128 * ASTR2;
        float* dB = Bs + st * 16 * BSTR2;
#pragma unroll
        for (int k = 0; k < 4; k++)
            cp16z(dA + ar[k]*ASTR2 + ac[k],
                  g_h + (size_t)(m0 + ar[k]) * CC + kk + ac[k], av[k]);
#pragma unroll
        for (int i = tid; i < 1024; i += 256) {
            int u = i >> 6, c4 = (i & 63) << 2;
            cp16(dB + u*BSTR2 + c4,
                 g_wqkv + (size_t)(kk/2 + u) * (2*N3C) + 2*n0 + c4);
        }
    };

    float cacc[2][8][4];
#pragma unroll
    for (int i = 0; i < 2; i++)
#pragma unroll
        for (int j = 0; j < 8; j++)
#pragma unroll
            for (int v = 0; v < 4; v++) cacc[i][j][v] = 0.f;

    stage(0, 0);
    CP_COMMIT();

    for (int t = 0; t < 32; t++) {
        int st = t & 1;
        if (t + 1 < 32) stage((t + 1) * 32, st ^ 1);
        CP_COMMIT();
        CP_WAIT1();
        __syncthreads();
        float* pA = As + st * 128 * ASTR2;
        float* pB = Bs + st * 16 * BSTR2;
#pragma unroll
        for (int ks2 = 0; ks2 < 4; ks2++) {
            const int k0 = ks2 * 8;
            unsigned af[2][4];
#pragma unroll
            for (int mf = 0; mf < 2; mf++) {
                int rbm = wm * 32 + mf * 16 + g;
                float2 t1 = *(float2*)&pA[rbm*ASTR2 + k0 + 2*tig];
                float2 t2 = *(float2*)&pA[(rbm+8)*ASTR2 + k0 + 2*tig];
                af[mf][0] = __float_as_uint(t1.x);
                af[mf][2] = __float_as_uint(t1.y);
                af[mf][1] = __float_as_uint(t2.x);
                af[mf][3] = __float_as_uint(t2.y);
            }
            const int ub = ks2 * 4 + tig;
#pragma unroll
            for (int nf = 0; nf < 8; nf++) {
                int nc = wn * 64 + nf * 8 + g;
                float2 bb = *(float2*)&pB[ub*BSTR2 + 2*nc];
                unsigned b0 = __float_as_uint(bb.x);
                unsigned b1 = __float_as_uint(bb.y);
                mma_tf32(cacc[0][nf], af[0], b0, b1);
                mma_tf32(cacc[1][nf], af[1], b0, b1);
            }
        }
        __syncthreads();
    }

#pragma unroll
    for (int mf = 0; mf < 2; mf++) {
        int r0 = m0 + wm * 32 + mf * 16 + g;
#pragma unroll
        for (int nf = 0; nf < 8; nf++) {
            int col = n0 + wn * 64 + nf * 8 + 2 * tig;
            if (r0 < MM)
                *(float2*)(g_qkv + (size_t)r0 * N3C + col) =
                    make_float2(cacc[mf][nf][0], cacc[mf][nf][1]);
            if (r0 + 8 < MM)
                *(float2*)(g_qkv + (size_t)(r0 + 8) * N3C + col) =
                    make_float2(cacc[mf][nf][2], cacc[mf][nf][3]);
        }
    }
}

__global__ __launch_bounds__(256) void gemm_out_mma(const float* __restrict__ bo,
                                                    float* __restrict__ out) {
    extern __shared__ float smg[];
    float* As = smg;
    float* Bs = smg + 2 * 128 * ASTR2;
    const int tid = threadIdx.x;
    const int lane = tid & 31, wid = tid >> 5;
    const int g = lane >> 2, tig = lane & 3;
    const int wm = wid & 3, wn = wid >> 2;
    const int m0 = blockIdx.y * 128;
    const int n0 = blockIdx.x * 128;

    int ar[4], ac[4]; bool av[4];
#pragma unroll
    for (int k = 0; k < 4; k++) {
        int i = tid + 256 * k;
        ar[k] = i >> 3; ac[k] = (i & 7) << 2;
        av[k] = (m0 + ar[k]) < MM;
    }

    auto stage = [&](int kk, int st) {
        float* dA = As + st * 128 * ASTR2;
        float* dB = Bs + st * 16 * BSTR2;
#pragma unroll
        for (int k = 0; k < 4; k++)
            cp16z(dA + ar[k]*ASTR2 + ac[k],
                  g_attn + (size_t)(m0 + ar[k]) * CC + kk + ac[k], av[k]);
#pragma unroll
        for (int i = tid; i < 1024; i += 256) {
            int u = i >> 6, c4 = (i & 63) << 2;
            cp16(dB + u*BSTR2 + c4,
                 g_wo + (size_t)(kk/2 + u) * (2*CC) + 2*n0 + c4);
        }
    };

    float cacc[2][8][4];
#pragma unroll
    for (int i = 0; i < 2; i++)
#pragma unroll
        for (int j = 0; j < 8; j++)
#pragma unroll
            for (int v = 0; v < 4; v++) cacc[i][j][v] = 0.f;

    stage(0, 0);
    CP_COMMIT();

    for (int t = 0; t < 32; t++) {
        int st = t & 1;
        if (t + 1 < 32) stage((t + 1) * 32, st ^ 1);
        CP_COMMIT();
        CP_WAIT1();
        __syncthreads();
        float* pA = As + st * 128 * ASTR2;
        float* pB = Bs + st * 16 * BSTR2;
#pragma unroll
        for (int ks2 = 0; ks2 < 4; ks2++) {
            const int k0 = ks2 * 8;
            unsigned af[2][4];
#pragma unroll
            for (int mf = 0; mf < 2; mf++) {
                int rbm = wm * 32 + mf * 16 + g;
                float2 t1 = *(float2*)&pA[rbm*ASTR2 + k0 + 2*tig];
                float2 t2 = *(float2*)&pA[(rbm+8)*ASTR2 + k0 + 2*tig];
                af[mf][0] = __float_as_uint(t1.x);
                af[mf][2] = __float_as_uint(t1.y);
                af[mf][1] = __float_as_uint(t2.x);
                af[mf][3] = __float_as_uint(t2.y);
            }
            const int ub = ks2 * 4 + tig;
#pragma unroll
            for (int nf = 0; nf < 8; nf++) {
                int nc = wn * 64 + nf * 8 + g;
                float2 bb = *(float2*)&pB[ub*BSTR2 + 2*nc];
                unsigned b0 = __float_as_uint(bb.x);
                unsigned b1 = __float_as_uint(bb.y);
                mma_tf32(cacc[0][nf], af[0], b0, b1);
                mma_tf32(cacc[1][nf], af[1], b0, b1);
            }
        }
        __syncthreads();
    }

#pragma unroll
    for (int mf = 0; mf < 2; mf++) {
#pragma unroll
        for (int half = 0; half < 2; half++) {
            int row = m0 + wm * 32 + mf * 16 + g + half * 8;
            if (row >= MM) continue;
            int b = row / SQ, s = row % SQ;
            size_t off = (s >= TEXT_N)
                ? ((size_t)(b * NTOK_N + (s - TEXT_N))) * CC
                : (size_t)BB * NTOK_N * CC + ((size_t)(b * TEXT_N + s)) * CC;
#pragma unroll
            for (int nf = 0; nf < 8; nf++) {
                int col = n0 + wn * 64 + nf * 8 + 2 * tig;
                float2 t = make_float2(cacc[mf][nf][0 + 2*half] + bo[col],
                                       cacc[mf][nf][1 + 2*half] + bo[col + 1]);
                *(float2*)(out + off + col) = t;
            }
        }
    }
}

// ---------------- combined norm: Q + KV ----------------
__global__ __launch_bounds__(512) void norm_kernel(const float* __restrict__ gq,
                                                   const float* __restrict__ bq,
                                                   const float* __restrict__ gk,
                                                   const float* __restrict__ bk,
                                                   const float* __restrict__ rc,
                                                   const float* __restrict__ rs,
                                                   const float* __restrict__ kc,
                                                   const float* __restrict__ vc,
                                                   const int* __restrict__ tok) {
    const int bid = blockIdx.x;
    const int w = threadIdx.x >> 5;
    const int lid = threadIdx.x & 31;

    if (bid < BB * SKV) {
        const int b = bid / SKV, p = bid % SKV;
        const float* ksrc; const float* vsrc;
        if (p < TEXT_N) {
            size_t row = ((size_t)(b * SQ + p)) * N3C;
            ksrc = g_qkv + row + CC; vsrc = g_qkv + row + 2*CC;
        } else {
            int i = g_inv[p - TEXT_N];
            if (i >= 0) {
                size_t row = ((size_t)(b * SQ + TEXT_N + i)) * N3C;
                ksrc = g_qkv + row + CC; vsrc = g_qkv + row + 2*CC;
            } else {
                size_t row = ((size_t)(b * SKV + p)) * CC;
                ksrc = kc + row; vsrc = vc + row;
            }
        }
        float2 x = *(const float2*)(ksrc + w * DD + 2 * lid);
        float sum = x.x + x.y;
        float sq  = x.x * x.x + x.y * x.y;
#pragma unroll
        for (int off = 16; off; off >>= 1) {
            sum += __shfl_xor_sync(0xffffffffu, sum, off);
            sq  += __shfl_xor_sync(0xffffffffu, sq,  off);
        }
        float mean = sum * (1.0f / 64.0f);
        float var  = sq * (1.0f / 64.0f) - mean * mean;
        float rsig = rsqrtf(var + 1e-6f);
        float y0 = (x.x - mean) * rsig * gk[2*lid]   + bk[2*lid];
        float y1 = (x.y - mean) * rsig * gk[2*lid+1] + bk[2*lid+1];
        float o0 = y0, o1 = y1;
        if (p >= TEXT_N) {
            int rp = p - TEXT_N;
            float2 c  = *(const float2*)(rc + (size_t)rp * DD + 2 * lid);
            float2 sn = *(const float2*)(rs + (size_t)rp * DD + 2 * lid);
            o0 = y0 * c.x - y1 * sn.x;
            o1 = y1 * c.y + y0 * sn.y;
        }
        int bh = b * HH + w;
        // K: col-paired within the 64-float row
        size_t kb = ((size_t)bh * SKVP + p) * DD;
        g_khead[kb + POSD(2*lid)]   = f2tff(o0);
        g_khead[kb + POSD(2*lid+1)] = f2tff(o1);
        // V: row-paired tile layout [bh][tile][unit32][2*d + half]
        float2 v = *(const float2*)(vsrc + w * DD + 2 * lid);
        int j = p & 63, tile = p >> 6;
        int u = ((j >> 3) << 2) | (j & 3);
        int half = (j >> 2) & 1;
        size_t vb = (((size_t)bh * NKT + tile) * 32 + u) * 128 + half;
        g_vhead[vb + 4*lid]     = f2tff(v.x);
        g_vhead[vb + 4*lid + 2] = f2tff(v.y);
    } else {
        const int bs = bid - BB * SKV;
        const int b = bs / SQ, s = bs % SQ;
        size_t base = (size_t)bs * N3C + w * DD + 2 * lid;
        float2 x = *(const float2*)(g_qkv + base);
        float sum = x.x + x.y;
        float sq  = x.x * x.x + x.y * x.y;
#pragma unroll
        for (int off = 16; off; off >>= 1) {
            sum += __shfl_xor_sync(0xffffffffu, sum, off);
            sq  += __shfl_xor_sync(0xffffffffu, sq,  off);
        }
        float mean = sum * (1.0f / 64.0f);
        float var  = sq * (1.0f / 64.0f) - mean * mean;
        float rsig = rsqrtf(var + 1e-6f);
        float y0 = (x.x - mean) * rsig * gq[2*lid]   + bq[2*lid];
        float y1 = (x.y - mean) * rsig * gq[2*lid+1] + bq[2*lid+1];
        float o0 = y0, o1 = y1;
        if (s >= TEXT_N) {
            int rp = tok[s - TEXT_N];
            float2 c  = *(const float2*)(rc + (size_t)rp * DD + 2 * lid);
            float2 sn = *(const float2*)(rs + (size_t)rp * DD + 2 * lid);
            o0 = y0 * c.x - y1 * sn.x;
            o1 = y1 * c.y + y0 * sn.y;
        }
        *(float2*)(g_qhead + ((size_t)(b * HH + w) * SQP + s) * DD + 2 * lid) =
            make_float2(f2tff(o0 * 0.125f), f2tff(o1 * 0.125f));
    }
}

// ---------------- flash attention: paired operands ----------------
#define KTSTR 72
#define VTSTR 136
#define PSTR  72
#define BUFSZ (64*KTSTR + 32*VTSTR)            /* 8960 floats */
#define PSOFF (2*BUFSZ)                         /* 17920 */
#define ATTN_SMEM ((PSOFF + 128*PSTR) * 4)      /* 108544 B */

__global__ __launch_bounds__(256, 2) void attn_mma_kernel() {
    extern __shared__ float sm[];
    float* Ps = sm + PSOFF;   // 128 x PSTR (Q staging, then P, col-paired)

    const int bh = blockIdx.x;
    const int qt = blockIdx.y;
    const int split = blockIdx.z;
    const int q0 = qt * 128;
    const int tid = threadIdx.x;
    const int w = tid >> 5, lane = tid & 31;
    const int g = lane >> 2, tig = lane & 3;
    const int rb = w * 16 + g;

    const float* kbase = g_khead + (size_t)bh * SKVP * DD;
    const float* vbase = g_vhead + (size_t)bh * SKVP * DD;  // tile layout
    const float* qbase = g_qhead + ((size_t)bh * SQP + q0) * DD;

    const int t0 = split * KSPLIT, t1 = t0 + KSPLIT;

    auto stage_kv = [&](float* dst, int t) {
#pragma unroll
        for (int i = tid; i < 2048; i += 256) {
            if (i < 1024) {
                int r = i >> 4, c4 = (i & 15) << 2;
                cp16(dst + r * KTSTR + c4,
                     kbase + (size_t)(t * 64 + r) * DD + c4);
            } else {
                int j = i - 1024;
                int u = j >> 5, c4 = (j & 31) << 2;
                cp16(dst + 64*KTSTR + u * VTSTR + c4,
                     vbase + ((size_t)t * 32 + u) * 128 + c4);
            }
        }
    };

    // stage Q (group 1), then first KV tile (group 2)
#pragma unroll
    for (int i = tid; i < 2048; i += 256) {
        int r = i >> 4, c4 = (i & 15) << 2;
        cp16(Ps + r * PSTR + c4, qbase + r * DD + c4);
    }
    CP_COMMIT();
    stage_kv(sm, t0);
    CP_COMMIT();
    CP_WAIT1();            // Q ready
    __syncthreads();

    unsigned qf[8][4];
#pragma unroll
    for (int ks = 0; ks < 8; ks++) {
        int k0 = ks * 8;
        qf[ks][0] = __float_as_uint(Ps[rb * PSTR + k0 + tig]);
        qf[ks][1] = __float_as_uint(Ps[(rb + 8) * PSTR + k0 + tig]);
        qf[ks][2] = __float_as_uint(Ps[rb * PSTR + k0 + tig + 4]);
        qf[ks][3] = __float_as_uint(Ps[(rb + 8) * PSTR + k0 + tig + 4]);
    }
    __syncthreads();   // Ps now reusable as P buffer

    float oacc[8][4];
#pragma unroll
    for (int nf = 0; nf < 8; nf++)
#pragma unroll
        for (int v = 0; v < 4; v++) oacc[nf][v] = 0.f;
    float mx0 = -1e30f, mx1 = -1e30f, l0 = 0.f, l1 = 0.f;

    // P store positions within each 8-col block (paired layout)
    const int pp0 = ((2*tig & 3) << 1) | ((2*tig >> 2) & 1);
    const int pp1 = (((2*tig+1) & 3) << 1) | (((2*tig+1) >> 2) & 1);

    for (int t = t0; t < t1; t++) {
        int st = (t - t0) & 1;
        if (t + 1 < t1) stage_kv(sm + (st ^ 1) * BUFSZ, t + 1);
        CP_COMMIT();
        CP_WAIT1();
        __syncthreads();
        float* Ks = sm + st * BUFSZ;
        float* Vs = Ks + 64 * KTSTR;
        const int kt = t * 64;

        // S = Q K^T  (paired K frags: one LDS.64 per mma)
        float sacc[8][4];
#pragma unroll
        for (int nf = 0; nf < 8; nf++)
#pragma unroll
            for (int v = 0; v < 4; v++) sacc[nf][v] = 0.f;
#pragma unroll
        for (int nf = 0; nf < 8; nf++) {
            int rn = (nf * 8 + g) * KTSTR + 2 * tig;
#pragma unroll
            for (int ks = 0; ks < 8; ks++) {
                float2 kk2 = *(float2*)&Ks[rn + ks * 8];
                mma_tf32(sacc[nf], qf[ks],
                         __float_as_uint(kk2.x), __float_as_uint(kk2.y));
            }
        }

        // mask tail columns
        if (kt + 64 > SKV) {
#pragma unroll
            for (int nf = 0; nf < 8; nf++) {
                int c = kt + nf * 8 + 2 * tig;
                if (c >= SKV)     { sacc[nf][0] = -1e30f; sacc[nf][2] = -1e30f; }
                if (c + 1 >= SKV) { sacc[nf][1] = -1e30f; sacc[nf][3] = -1e30f; }
            }
        }

        // online softmax (rows rb, rb+8)
        float tmax0 = -1e30f, tmax1 = -1e30f;
#pragma unroll
        for (int nf = 0; nf < 8; nf++) {
            tmax0 = fmaxf(tmax0, fmaxf(sacc[nf][0], sacc[nf][1]));
            tmax1 = fmaxf(tmax1, fmaxf(sacc[nf][2], sacc[nf][3]));
        }
        tmax0 = fmaxf(tmax0, __shfl_xor_sync(0xffffffffu, tmax0, 1));
        tmax0 = fmaxf(tmax0, __shfl_xor_sync(0xffffffffu, tmax0, 2));
        tmax1 = fmaxf(tmax1, __shfl_xor_sync(0xffffffffu, tmax1, 1));
        tmax1 = fmaxf(tmax1, __shfl_xor_sync(0xffffffffu, tmax1, 2));
        float mn0 = fmaxf(mx0, tmax0), mn1 = fmaxf(mx1, tmax1);
        float corr0 = __expf(mx0 - mn0), corr1 = __expf(mx1 - mn1);
        mx0 = mn0; mx1 = mn1;

        float tsum0 = 0.f, tsum1 = 0.f;
#pragma unroll
        for (int nf = 0; nf < 8; nf++) {
            float p00 = __expf(sacc[nf][0] - mn0);
            float p01 = __expf(sacc[nf][1] - mn0);
            float p10 = __expf(sacc[nf][2] - mn1);
            float p11 = __expf(sacc[nf][3] - mn1);
            tsum0 += p00 + p01; tsum1 += p10 + p11;
            int cb = nf * 8;
            Ps[rb * PSTR + cb + pp0]       = f2tff(p00);
            Ps[rb * PSTR + cb + pp1]       = f2tff(p01);
            Ps[(rb + 8) * PSTR + cb + pp0] = f2tff(p10);
            Ps[(rb + 8) * PSTR + cb + pp1] = f2tff(p11);
        }
        tsum0 += __shfl_xor_sync(0xffffffffu, tsum0, 1);
        tsum0 += __shfl_xor_sync(0xffffffffu, tsum0, 2);
        tsum1 += __shfl_xor_sync(0xffffffffu, tsum1, 1);
        tsum1 += __shfl_xor_sync(0xffffffffu, tsum1, 2);
        l0 = l0 * corr0 + tsum0;
        l1 = l1 * corr1 + tsum1;
#pragma unroll
        for (int nf = 0; nf < 8; nf++) {
            oacc[nf][0] *= corr0; oacc[nf][1] *= corr0;
            oacc[nf][2] *= corr1; oacc[nf][3] *= corr1;
        }
        __syncwarp();

        // O += P V  (paired P frags + paired V rows: LDS.64 everywhere)
#pragma unroll
        for (int ks = 0; ks < 8; ks++) {
            int j0 = ks * 8;
            float2 pa1 = *(float2*)&Ps[rb * PSTR + j0 + 2*tig];
            float2 pa2 = *(float2*)&Ps[(rb + 8) * PSTR + j0 + 2*tig];
            unsigned pf[4];
            pf[0] = __float_as_uint(pa1.x);
            pf[2] = __float_as_uint(pa1.y);
            pf[1] = __float_as_uint(pa2.x);
            pf[3] = __float_as_uint(pa2.y);
            const int ub = (ks * 4 + tig) * VTSTR + 2 * g;
#pragma unroll
            for (int nf = 0; nf < 8; nf++) {
                float2 vv = *(float2*)&Vs[ub + 16 * nf];
                mma_tf32(oacc[nf], pf,
                         __float_as_uint(vv.x), __float_as_uint(vv.y));
            }
        }
        __syncthreads();
    }

    // split epilogue: unnormalized O + (m, l)
    const int bhqt = bh * NQT + qt;
    const size_t obase = ((size_t)(split * 32 * NQT + bhqt)) * 128 * 64;
#pragma unroll
    for (int nf = 0; nf < 8; nf++) {
        int col = nf * 8 + 2 * tig;
        *(float2*)(g_op + obase + (size_t)rb * 64 + col) =
            make_float2(oacc[nf][0], oacc[nf][1]);
        *(float2*)(g_op + obase + (size_t)(rb + 8) * 64 + col) =
            make_float2(oacc[nf][2], oacc[nf][3]);
    }
    if (tig == 0) {
        size_t mb = ((size_t)(split * 32 * NQT + bhqt)) * 128 * 2;
        g_ml[mb + rb * 2]           = mx0;
        g_ml[mb + rb * 2 + 1]       = l0;
        g_ml[mb + (rb + 8) * 2]     = mx1;
        g_ml[mb + (rb + 8) * 2 + 1] = l1;
    }
}

// ---------------- merge the two KV splits (writes rounded, col-paired g_attn) ----
__global__ void attn_merge_kernel() {
    int idx = blockIdx.x * blockDim.x + threadIdx.x;
    const int total = 32 * NQT * 128 * 32;
    if (idx >= total) return;
    int lane = idx & 31;
    int row = idx >> 5;
    int r = row & 127;
    int bhqt = row >> 7;
    int qt = bhqt % NQT, bh = bhqt / NQT;
    int qr = qt * 128 + r;
    if (qr >= SQ) return;
    size_t mb0 = (size_t)bhqt * 256 + r * 2;
    size_t mb1 = (size_t)(32 * NQT + bhqt) * 256 + r * 2;
    float m0 = g_ml[mb0], la = g_ml[mb0 + 1];
    float m1 = g_ml[mb1], lb = g_ml[mb1 + 1];
    float m = fmaxf(m0, m1);
    float c0 = __expf(m0 - m), c1 = __expf(m1 - m);
    float inv = 1.0f / (la * c0 + lb * c1);
    float2 a = *(const float2*)(g_op + ((size_t)bhqt * 128 + r) * 64 + 2 * lane);
    float2 bv = *(const float2*)(g_op + ((size_t)(32 * NQT + bhqt) * 128 + r) * 64 + 2 * lane);
    int b = bh >> 4, h = bh & 15;
    float* dst = g_attn + ((size_t)(b * SQ + qr)) * CC + h * DD;
    dst[POSD(2*lane)]   = f2tff((a.x * c0 + bv.x * c1) * inv);
    dst[POSD(2*lane+1)] = f2tff((a.y * c0 + bv.y * c1) * inv);
}

// ---------------- launch ----------------
extern "C" void kernel_launch(void* const* d_in, const int* in_sizes, int n_in,
                              void* d_out, int out_size) {
    const float* hid = (const float*)d_in[0];
    const float* enc = (const float*)d_in[1];
    const float* Wq  = (const float*)d_in[2];
    const float* Wk  = (const float*)d_in[3];
    const float* Wv  = (const float*)d_in[4];
    const float* Wo  = (const float*)d_in[5];
    const float* bo  = (const float*)d_in[6];
    const float* gq  = (const float*)d_in[7];
    const float* bq  = (const float*)d_in[8];
    const float* gk  = (const float*)d_in[9];
    const float* bk  = (const float*)d_in[10];
    const float* rc  = (const float*)d_in[11];
    const float* rs  = (const float*)d_in[12];
    const float* kc  = (const float*)d_in[13];
    const float* vc  = (const float*)d_in[14];
    const int*   tok = (const int*)d_in[15];
    float* out = (float*)d_out;

    cudaFuncSetAttribute(gemm_qkv_mma,
                         cudaFuncAttributeMaxDynamicSharedMemorySize, GEMM_SMEM);
    cudaFuncSetAttribute(gemm_out_mma,
                         cudaFuncAttributeMaxDynamicSharedMemorySize, GEMM_SMEM);
    cudaFuncSetAttribute(attn_mma_kernel,
                         cudaFuncAttributeMaxDynamicSharedMemorySize, ATTN_SMEM);

    inv_init_kernel<<<(TOK_N + 255) / 256, 256>>>();                       // 1
    inv_scatter_kernel<<<(NTOK_N + 255) / 256, 256>>>(tok);                // 2
    prep_kernel<<<(PT3 + 255) / 256, 256>>>(hid, enc, Wq, Wk, Wv, Wo);     // 3
    gemm_qkv_mma<<<dim3(N3C / 128, (MM + 127) / 128), 256, GEMM_SMEM>>>(); // 4
    norm_kernel<<<BB * SKV + BB * SQ, 512>>>(gq, bq, gk, bk, rc, rs,
                                             kc, vc, tok);                 // 5
    attn_mma_kernel<<<dim3(BB * HH, NQT, 2), 256, ATTN_SMEM>>>();          // 6
    attn_merge_kernel<<<(32 * NQT * 128 * 32 + 255) / 256, 256>>>();       // 7
    gemm_out_mma<<<dim3(CC / 128, (MM + 127) / 128), 256, GEMM_SMEM>>>(bo, out); // 8
}

// round 9
// speedup vs baseline: 1.7533x; 1.7533x over previous
#include <cuda_runtime.h>
#include <cuda_fp16.h>
#include <math.h>

#define BB 2
#define HH 16
#define DD 64
#define CC 1024
#define TEXT_N 226
#define NTOK_N 1024
#define TOK_N 4096
#define SQ (TEXT_N + NTOK_N)   /* 1250 */
#define SKV (TEXT_N + TOK_N)   /* 4322 */
#define N3C (3*CC)             /* 3072 */
#define SQP 1280
#define SKVP 4352
#define NKT 68
#define KSPLIT 34
#define NQT 10
#define MM (BB * SQ)           /* 2500 */

// ---------------- scratch (zero-initialized at module load) ----------------
__device__ __half g_h     [MM * CC];              // A of QKV gemm (half)
__device__ __half g_wqkvT [N3C * CC];             // W^T rows n, k contiguous
__device__ __half g_woT   [CC * CC];              // Wo^T
__device__ float  g_qkv   [MM * N3C];             // QKV gemm out (fp32)
__device__ __half g_khead [BB * HH * SKVP * DD];  // K heads, natural [j][d]
__device__ __half g_vtmp  [BB * HH * SKVP * DD];  // V heads, natural
__device__ __half g_vheadT[BB * HH * DD * SKVP];  // V^T [d][j]
__device__ __half g_qhead [BB * HH * SQP * DD];   // Q*0.125
__device__ __half g_attn  [MM * CC];              // attention out (half)
__device__ int    g_inv   [TOK_N];
__device__ float  g_ml    [2 * 32 * NQT * 128 * 2];
__device__ float  g_op    [2 * 32 * NQT * 128 * 64];

// ---------------- helpers ----------------
__device__ __forceinline__ unsigned h2u(half2 h) {
    union { half2 h; unsigned u; } cvt;
    cvt.h = h;
    return cvt.u;
}
__device__ __forceinline__ void mma16(float* c, const unsigned* a,
                                      unsigned b0, unsigned b1) {
    asm volatile(
        "mma.sync.aligned.m16n8k16.row.col.f32.f16.f16.f32 "
        "{%0,%1,%2,%3}, {%4,%5,%6,%7}, {%8,%9}, {%0,%1,%2,%3};"
        : "+f"(c[0]), "+f"(c[1]), "+f"(c[2]), "+f"(c[3])
        : "r"(a[0]), "r"(a[1]), "r"(a[2]), "r"(a[3]), "r"(b0), "r"(b1));
}
__device__ __forceinline__ void cp16(void* smem_dst, const void* gsrc) {
    unsigned sa = (unsigned)__cvta_generic_to_shared(smem_dst);
    asm volatile("cp.async.cg.shared.global [%0], [%1], 16;" :: "r"(sa), "l"(gsrc));
}
__device__ __forceinline__ void cp16z(void* smem_dst, const void* gsrc, bool pred) {
    unsigned sa = (unsigned)__cvta_generic_to_shared(smem_dst);
    int sz = pred ? 16 : 0;
    asm volatile("cp.async.cg.shared.global [%0], [%1], 16, %2;"
                 :: "r"(sa), "l"(gsrc), "r"(sz));
}
#define CP_COMMIT() asm volatile("cp.async.commit_group;")
#define CP_WAIT0()  asm volatile("cp.async.wait_group 0;")

// ---------------- inverse token map ----------------
__global__ void inv_init_kernel() {
    int i = blockIdx.x * blockDim.x + threadIdx.x;
    if (i < TOK_N) g_inv[i] = -1;
}
__global__ void inv_scatter_kernel(const int* __restrict__ tok) {
    int i = blockIdx.x * blockDim.x + threadIdx.x;
    if (i < NTOK_N) atomicMax(&g_inv[tok[i]], i);
}

// ---------------- prep: h -> half (natural layout) ----------------
__global__ void prep_h_kernel(const float* __restrict__ hid,
                              const float* __restrict__ enc) {
    int i = blockIdx.x * blockDim.x + threadIdx.x;
    const int tot = MM * CC / 4;
    if (i >= tot) return;
    int r = i / (CC / 4), c4 = (i % (CC / 4)) * 4;
    int b = r / SQ, s = r % SQ;
    const float* src = (s < TEXT_N)
        ? enc + ((size_t)b * TEXT_N + s) * CC + c4
        : hid + ((size_t)b * NTOK_N + (s - TEXT_N)) * CC + c4;
    float4 v = *(const float4*)src;
    __half* d = g_h + (size_t)r * CC + c4;
    *(  half2*)(d)     = __floats2half2_rn(v.x, v.y);
    *(  half2*)(d + 2) = __floats2half2_rn(v.z, v.w);
}

// ---------------- prep: tiled transpose of weights -> half [n][k] ----------------
__global__ __launch_bounds__(256) void prep_wt_kernel(const float* __restrict__ Wq,
                                                      const float* __restrict__ Wk,
                                                      const float* __restrict__ Wv,
                                                      const float* __restrict__ Wo) {
    __shared__ float ts[32][33];
    int bid = blockIdx.x;
    const float* W; __half* dst; int k0, nbase, ncol;
    if (bid < 3072) {              // wqkvT: 32 k-tiles x 96 n-tiles
        int kt = bid / 96, nt = bid % 96;
        k0 = kt * 32;
        nbase = nt * 32;
        W = (nt < 32) ? Wq : (nt < 64) ? Wk : Wv;
        ncol = (nt % 32) * 32;
        dst = g_wqkvT;
    } else {                       // woT: 32 x 32
        int b2 = bid - 3072;
        int kt = b2 / 32, nt = b2 % 32;
        k0 = kt * 32;
        nbase = nt * 32;
        ncol = nt * 32;
        W = Wo;
        dst = g_woT;
    }
    int rr = threadIdx.x >> 5, c = threadIdx.x & 31;
#pragma unroll
    for (int it = 0; it < 4; it++)
        ts[rr + 8 * it][c] = W[(size_t)(k0 + rr + 8 * it) * CC + ncol + c];
    __syncthreads();
#pragma unroll
    for (int it = 0; it < 4; it++) {
        int n = nbase + rr + 8 * it;
        dst[(size_t)n * CC + k0 + c] = __float2half_rn(ts[c][rr + 8 * it]);
    }
}

// ---------------- GEMMs: fp16 mma, 128x128 block, K-tile 32 ----------------
#define ASTRH 40
#define GEMM_SMEM ((2*128*ASTRH + 2*128*ASTRH) * 2)   /* 40960 B */

__device__ __forceinline__ void gemm_body(const __half* gA, const __half* gB,
                                          int m0, int n0, float cacc[2][8][4],
                                          int lane, int wid) {
    extern __shared__ __half smg[];
    __half* As = smg;
    __half* Bs = smg + 2 * 128 * ASTRH;
    const int tid = threadIdx.x;
    const int g = (lane >> 2), tig = lane & 3;
    const int wm = wid & 3, wn = wid >> 2;

    auto stage = [&](int kk, int st) {
        __half* dA = As + st * 128 * ASTRH;
        __half* dB = Bs + st * 128 * ASTRH;
#pragma unroll
        for (int i = tid; i < 1024; i += 256) {
            if (i < 512) {
                int r = i >> 2, c8 = (i & 3) * 8;
                cp16z(dA + r * ASTRH + c8,
                      gA + (size_t)(m0 + r) * CC + kk + c8, (m0 + r) < MM);
            } else {
                int j = i - 512;
                int r = j >> 2, c8 = (j & 3) * 8;
                cp16(dB + r * ASTRH + c8,
                     gB + (size_t)(n0 + r) * CC + kk + c8);
            }
        }
    };

    stage(0, 0);
    CP_COMMIT();

    for (int t = 0; t < 32; t++) {
        int st = t & 1;
        CP_WAIT0();
        __syncthreads();
        if (t + 1 < 32) { stage((t + 1) * 32, st ^ 1); CP_COMMIT(); }
        __half* pA = As + st * 128 * ASTRH;
        __half* pB = Bs + st * 128 * ASTRH;
#pragma unroll
        for (int ks = 0; ks < 2; ks++) {
            const int k0 = ks * 16;
            unsigned af[2][4];
#pragma unroll
            for (int mf = 0; mf < 2; mf++) {
                int rbm = wm * 32 + mf * 16 + g;
                af[mf][0] = *(const unsigned*)&pA[rbm * ASTRH + k0 + 2*tig];
                af[mf][1] = *(const unsigned*)&pA[(rbm+8) * ASTRH + k0 + 2*tig];
                af[mf][2] = *(const unsigned*)&pA[rbm * ASTRH + k0 + 8 + 2*tig];
                af[mf][3] = *(const unsigned*)&pA[(rbm+8) * ASTRH + k0 + 8 + 2*tig];
            }
#pragma unroll
            for (int nf = 0; nf < 8; nf++) {
                int nr = wn * 64 + nf * 8 + g;
                unsigned b0 = *(const unsigned*)&pB[nr * ASTRH + k0 + 2*tig];
                unsigned b1 = *(const unsigned*)&pB[nr * ASTRH + k0 + 8 + 2*tig];
                mma16(cacc[0][nf], af[0], b0, b1);
                mma16(cacc[1][nf], af[1], b0, b1);
            }
        }
    }
}

__global__ __launch_bounds__(256) void gemm_qkv_mma() {
    const int lane = threadIdx.x & 31, wid = threadIdx.x >> 5;
    const int g = lane >> 2, tig = lane & 3;
    const int wm = wid & 3, wn = wid >> 2;
    const int m0 = blockIdx.y * 128, n0 = blockIdx.x * 128;
    float cacc[2][8][4];
#pragma unroll
    for (int i = 0; i < 2; i++)
#pragma unroll
        for (int j = 0; j < 8; j++)
#pragma unroll
            for (int v = 0; v < 4; v++) cacc[i][j][v] = 0.f;
    gemm_body(g_h, g_wqkvT, m0, n0, cacc, lane, wid);
#pragma unroll
    for (int mf = 0; mf < 2; mf++) {
        int r0 = m0 + wm * 32 + mf * 16 + g;
#pragma unroll
        for (int nf = 0; nf < 8; nf++) {
            int col = n0 + wn * 64 + nf * 8 + 2 * tig;
            if (r0 < MM)
                *(float2*)(g_qkv + (size_t)r0 * N3C + col) =
                    make_float2(cacc[mf][nf][0], cacc[mf][nf][1]);
            if (r0 + 8 < MM)
                *(float2*)(g_qkv + (size_t)(r0 + 8) * N3C + col) =
                    make_float2(cacc[mf][nf][2], cacc[mf][nf][3]);
        }
    }
}

__global__ __launch_bounds__(256) void gemm_out_mma(const float* __restrict__ bo,
                                                    float* __restrict__ out) {
    const int lane = threadIdx.x & 31, wid = threadIdx.x >> 5;
    const int g = lane >> 2, tig = lane & 3;
    const int wm = wid & 3, wn = wid >> 2;
    const int m0 = blockIdx.y * 128, n0 = blockIdx.x * 128;
    float cacc[2][8][4];
#pragma unroll
    for (int i = 0; i < 2; i++)
#pragma unroll
        for (int j = 0; j < 8; j++)
#pragma unroll
            for (int v = 0; v < 4; v++) cacc[i][j][v] = 0.f;
    gemm_body(g_attn, g_woT, m0, n0, cacc, lane, wid);
#pragma unroll
    for (int mf = 0; mf < 2; mf++) {
#pragma unroll
        for (int half_ = 0; half_ < 2; half_++) {
            int row = m0 + wm * 32 + mf * 16 + g + half_ * 8;
            if (row >= MM) continue;
            int b = row / SQ, s = row % SQ;
            size_t off = (s >= TEXT_N)
                ? ((size_t)(b * NTOK_N + (s - TEXT_N))) * CC
                : (size_t)BB * NTOK_N * CC + ((size_t)(b * TEXT_N + s)) * CC;
#pragma unroll
            for (int nf = 0; nf < 8; nf++) {
                int col = n0 + wn * 64 + nf * 8 + 2 * tig;
                float2 t = make_float2(cacc[mf][nf][0 + 2*half_] + bo[col],
                                       cacc[mf][nf][1 + 2*half_] + bo[col + 1]);
                *(float2*)(out + off + col) = t;
            }
        }
    }
}

// ---------------- combined norm: Q + KV, half outputs ----------------
__global__ __launch_bounds__(512) void norm_kernel(const float* __restrict__ gq,
                                                   const float* __restrict__ bq,
                                                   const float* __restrict__ gk,
                                                   const float* __restrict__ bk,
                                                   const float* __restrict__ rc,
                                                   const float* __restrict__ rs,
                                                   const float* __restrict__ kc,
                                                   const float* __restrict__ vc,
                                                   const int* __restrict__ tok) {
    const int bid = blockIdx.x;
    const int w = threadIdx.x >> 5;
    const int lid = threadIdx.x & 31;

    if (bid < BB * SKV) {
        const int b = bid / SKV, p = bid % SKV;
        const float* ksrc; const float* vsrc;
        if (p < TEXT_N) {
            size_t row = ((size_t)(b * SQ + p)) * N3C;
            ksrc = g_qkv + row + CC; vsrc = g_qkv + row + 2*CC;
        } else {
            int i = g_inv[p - TEXT_N];
            if (i >= 0) {
                size_t row = ((size_t)(b * SQ + TEXT_N + i)) * N3C;
                ksrc = g_qkv + row + CC; vsrc = g_qkv + row + 2*CC;
            } else {
                size_t row = ((size_t)(b * SKV + p)) * CC;
                ksrc = kc + row; vsrc = vc + row;
            }
        }
        float2 x = *(const float2*)(ksrc + w * DD + 2 * lid);
        float sum = x.x + x.y;
        float sq  = x.x * x.x + x.y * x.y;
#pragma unroll
        for (int off = 16; off; off >>= 1) {
            sum += __shfl_xor_sync(0xffffffffu, sum, off);
            sq  += __shfl_xor_sync(0xffffffffu, sq,  off);
        }
        float mean = sum * (1.0f / 64.0f);
        float var  = sq * (1.0f / 64.0f) - mean * mean;
        float rsig = rsqrtf(var + 1e-6f);
        float y0 = (x.x - mean) * rsig * gk[2*lid]   + bk[2*lid];
        float y1 = (x.y - mean) * rsig * gk[2*lid+1] + bk[2*lid+1];
        float o0 = y0, o1 = y1;
        if (p >= TEXT_N) {
            int rp = p - TEXT_N;
            float2 c  = *(const float2*)(rc + (size_t)rp * DD + 2 * lid);
            float2 sn = *(const float2*)(rs + (size_t)rp * DD + 2 * lid);
            o0 = y0 * c.x - y1 * sn.x;
            o1 = y1 * c.y + y0 * sn.y;
        }
        int bh = b * HH + w;
        size_t ob = ((size_t)bh * SKVP + p) * DD + 2 * lid;
        *(half2*)(g_khead + ob) = __floats2half2_rn(o0, o1);
        float2 v = *(const float2*)(vsrc + w * DD + 2 * lid);
        *(half2*)(g_vtmp + ob) = __floats2half2_rn(v.x, v.y);
    } else {
        const int bs = bid - BB * SKV;
        const int b = bs / SQ, s = bs % SQ;
        size_t base = (size_t)bs * N3C + w * DD + 2 * lid;
        float2 x = *(const float2*)(g_qkv + base);
        float sum = x.x + x.y;
        float sq  = x.x * x.x + x.y * x.y;
#pragma unroll
        for (int off = 16; off; off >>= 1) {
            sum += __shfl_xor_sync(0xffffffffu, sum, off);
            sq  += __shfl_xor_sync(0xffffffffu, sq,  off);
        }
        float mean = sum * (1.0f / 64.0f);
        float var  = sq * (1.0f / 64.0f) - mean * mean;
        float rsig = rsqrtf(var + 1e-6f);
        float y0 = (x.x - mean) * rsig * gq[2*lid]   + bq[2*lid];
        float y1 = (x.y - mean) * rsig * gq[2*lid+1] + bq[2*lid+1];
        float o0 = y0, o1 = y1;
        if (s >= TEXT_N) {
            int rp = tok[s - TEXT_N];
            float2 c  = *(const float2*)(rc + (size_t)rp * DD + 2 * lid);
            float2 sn = *(const float2*)(rs + (size_t)rp * DD + 2 * lid);
            o0 = y0 * c.x - y1 * sn.x;
            o1 = y1 * c.y + y0 * sn.y;
        }
        *(half2*)(g_qhead + ((size_t)(b * HH + w) * SQP + s) * DD + 2 * lid) =
            __floats2half2_rn(o0 * 0.125f, o1 * 0.125f);
    }
}

// ---------------- V transpose: [bh][j][d] half -> [bh][d][j] half ----------------
__global__ __launch_bounds__(256) void transpose_v_kernel() {
    __shared__ __half ts[64 * 65];
    const int bid = blockIdx.x;
    const int bh = bid / NKT, t = bid % NKT;
    const __half* src = g_vtmp + ((size_t)bh * SKVP + t * 64) * DD;
    const int tid = threadIdx.x;
#pragma unroll
    for (int i = tid; i < 2048; i += 256) {
        int j = i >> 5, d2 = (i & 31) * 2;
        half2 v = *(const half2*)&src[j * DD + d2];
        ts[d2 * 65 + j]       = __low2half(v);
        ts[(d2 + 1) * 65 + j] = __high2half(v);
    }
    __syncthreads();
    __half* dst = g_vheadT + (size_t)bh * DD * SKVP + t * 64;
#pragma unroll
    for (int i = tid; i < 2048; i += 256) {
        int d = i >> 5, j2 = (i & 31) * 2;
        *(half2*)&dst[(size_t)d * SKVP + j2] =
            __halves2half2(ts[d * 65 + j2], ts[d * 65 + j2 + 1]);
    }
}

// ---------------- flash attention: fp16 mma, P register-resident ----------------
#define KSTR 72
#define KBUF (64 * KSTR)                 /* 4608 halves per K or V tile */
#define QSOFF (4 * KBUF)                 /* 18432 */
#define ATTN_SMEM ((QSOFF + 128 * KSTR) * 2)   /* 55296 B */

__global__ __launch_bounds__(256, 2) void attn_mma_kernel() {
    extern __shared__ __half sm16[];
    __half* Qs = sm16 + QSOFF;

    const int bh = blockIdx.x;
    const int qt = blockIdx.y;
    const int split = blockIdx.z;
    const int q0 = qt * 128;
    const int tid = threadIdx.x;
    const int w = tid >> 5, lane = tid & 31;
    const int g = lane >> 2, tig = lane & 3;
    const int rb = w * 16 + g;

    const __half* kbase = g_khead  + (size_t)bh * SKVP * DD;
    const __half* vtbase = g_vheadT + (size_t)bh * DD * SKVP;
    const __half* qbase = g_qhead  + ((size_t)bh * SQP + q0) * DD;

    const int t0 = split * KSPLIT, t1 = t0 + KSPLIT;

    auto stage_kv = [&](__half* dst, int t) {
#pragma unroll
        for (int i = tid; i < 1024; i += 256) {
            if (i < 512) {
                int j = i >> 3, c8 = (i & 7) * 8;
                cp16(dst + j * KSTR + c8, kbase + (size_t)(t * 64 + j) * DD + c8);
            } else {
                int i2 = i - 512;
                int d = i2 >> 3, c8 = (i2 & 7) * 8;
                cp16(dst + KBUF + d * KSTR + c8,
                     vtbase + (size_t)d * SKVP + t * 64 + c8);
            }
        }
    };

    // stage Q + first KV tile
#pragma unroll
    for (int i = tid; i < 1024; i += 256) {
        int r = i >> 3, c8 = (i & 7) * 8;
        cp16(Qs + r * KSTR + c8, qbase + r * DD + c8);
    }
    stage_kv(sm16, t0);
    CP_COMMIT();
    CP_WAIT0();
    __syncthreads();

    unsigned qf[4][4];
#pragma unroll
    for (int ks = 0; ks < 4; ks++) {
        int k0 = ks * 16;
        qf[ks][0] = *(const unsigned*)&Qs[rb * KSTR + k0 + 2*tig];
        qf[ks][1] = *(const unsigned*)&Qs[(rb + 8) * KSTR + k0 + 2*tig];
        qf[ks][2] = *(const unsigned*)&Qs[rb * KSTR + k0 + 8 + 2*tig];
        qf[ks][3] = *(const unsigned*)&Qs[(rb + 8) * KSTR + k0 + 8 + 2*tig];
    }

    float oacc[8][4];
#pragma unroll
    for (int nf = 0; nf < 8; nf++)
#pragma unroll
        for (int v = 0; v < 4; v++) oacc[nf][v] = 0.f;
    float mx0 = -1e30f, mx1 = -1e30f, l0 = 0.f, l1 = 0.f;

    if (t0 + 1 < t1) { stage_kv(sm16 + 2 * KBUF, t0 + 1); CP_COMMIT(); }

    for (int t = t0; t < t1; t++) {
        int st = (t - t0) & 1;
        __half* Ks = sm16 + st * (2 * KBUF);
        __half* Vs = Ks + KBUF;
        const int kt = t * 64;

        // S = Q K^T   (K natural [j][d]: b-frags are consecutive-d half2s)
        float sacc[8][4];
#pragma unroll
        for (int nf = 0; nf < 8; nf++)
#pragma unroll
            for (int v = 0; v < 4; v++) sacc[nf][v] = 0.f;
#pragma unroll
        for (int nf = 0; nf < 8; nf++) {
            int rn = (nf * 8 + g) * KSTR;
#pragma unroll
            for (int ks = 0; ks < 4; ks++) {
                unsigned b0 = *(const unsigned*)&Ks[rn + 16*ks + 2*tig];
                unsigned b1 = *(const unsigned*)&Ks[rn + 16*ks + 8 + 2*tig];
                mma16(sacc[nf], qf[ks], b0, b1);
            }
        }

        // mask tail columns
        if (kt + 64 > SKV) {
#pragma unroll
            for (int nf = 0; nf < 8; nf++) {
                int c = kt + nf * 8 + 2 * tig;
                if (c >= SKV)     { sacc[nf][0] = -1e30f; sacc[nf][2] = -1e30f; }
                if (c + 1 >= SKV) { sacc[nf][1] = -1e30f; sacc[nf][3] = -1e30f; }
            }
        }

        // online softmax (rows rb, rb+8); write p back into sacc
        float tmax0 = -1e30f, tmax1 = -1e30f;
#pragma unroll
        for (int nf = 0; nf < 8; nf++) {
            tmax0 = fmaxf(tmax0, fmaxf(sacc[nf][0], sacc[nf][1]));
            tmax1 = fmaxf(tmax1, fmaxf(sacc[nf][2], sacc[nf][3]));
        }
        tmax0 = fmaxf(tmax0, __shfl_xor_sync(0xffffffffu, tmax0, 1));
        tmax0 = fmaxf(tmax0, __shfl_xor_sync(0xffffffffu, tmax0, 2));
        tmax1 = fmaxf(tmax1, __shfl_xor_sync(0xffffffffu, tmax1, 1));
        tmax1 = fmaxf(tmax1, __shfl_xor_sync(0xffffffffu, tmax1, 2));
        float mn0 = fmaxf(mx0, tmax0), mn1 = fmaxf(mx1, tmax1);
        float corr0 = __expf(mx0 - mn0), corr1 = __expf(mx1 - mn1);
        mx0 = mn0; mx1 = mn1;

        float tsum0 = 0.f, tsum1 = 0.f;
#pragma unroll
        for (int nf = 0; nf < 8; nf++) {
            sacc[nf][0] = __expf(sacc[nf][0] - mn0);
            sacc[nf][1] = __expf(sacc[nf][1] - mn0);
            sacc[nf][2] = __expf(sacc[nf][2] - mn1);
            sacc[nf][3] = __expf(sacc[nf][3] - mn1);
            tsum0 += sacc[nf][0] + sacc[nf][1];
            tsum1 += sacc[nf][2] + sacc[nf][3];
        }
        tsum0 += __shfl_xor_sync(0xffffffffu, tsum0, 1);
        tsum0 += __shfl_xor_sync(0xffffffffu, tsum0, 2);
        tsum1 += __shfl_xor_sync(0xffffffffu, tsum1, 1);
        tsum1 += __shfl_xor_sync(0xffffffffu, tsum1, 2);
        l0 = l0 * corr0 + tsum0;
        l1 = l1 * corr1 + tsum1;
#pragma unroll
        for (int nf = 0; nf < 8; nf++) {
            oacc[nf][0] *= corr0; oacc[nf][1] *= corr0;
            oacc[nf][2] *= corr1; oacc[nf][3] *= corr1;
        }

        // O += P V  — P fragments packed straight from registers (no smem)
#pragma unroll
        for (int ks = 0; ks < 4; ks++) {
            unsigned pf[4];
            pf[0] = h2u(__floats2half2_rn(sacc[2*ks][0],   sacc[2*ks][1]));
            pf[1] = h2u(__floats2half2_rn(sacc[2*ks][2],   sacc[2*ks][3]));
            pf[2] = h2u(__floats2half2_rn(sacc[2*ks+1][0], sacc[2*ks+1][1]));
            pf[3] = h2u(__floats2half2_rn(sacc[2*ks+1][2], sacc[2*ks+1][3]));
#pragma unroll
            for (int nf = 0; nf < 8; nf++) {
                int rn = (nf * 8 + g) * KSTR;
                unsigned b0 = *(const unsigned*)&Vs[rn + 16*ks + 2*tig];
                unsigned b1 = *(const unsigned*)&Vs[rn + 16*ks + 8 + 2*tig];
                mma16(oacc[nf], pf, b0, b1);
            }
        }

        // pipeline: wait next tile's data, then stage tile t+2 into this buffer
        if (t + 1 < t1) {
            CP_WAIT0();
            __syncthreads();
            if (t + 2 < t1) { stage_kv(sm16 + st * (2 * KBUF), t + 2); CP_COMMIT(); }
        }
    }

    // split epilogue: unnormalized O + (m, l)
    const int bhqt = bh * NQT + qt;
    const size_t obase = ((size_t)(split * 32 * NQT + bhqt)) * 128 * 64;
#pragma unroll
    for (int nf = 0; nf < 8; nf++) {
        int col = nf * 8 + 2 * tig;
        *(float2*)(g_op + obase + (size_t)rb * 64 + col) =
            make_float2(oacc[nf][0], oacc[nf][1]);
        *(float2*)(g_op + obase + (size_t)(rb + 8) * 64 + col) =
            make_float2(oacc[nf][2], oacc[nf][3]);
    }
    if (tig == 0) {
        size_t mb = ((size_t)(split * 32 * NQT + bhqt)) * 128 * 2;
        g_ml[mb + rb * 2]           = mx0;
        g_ml[mb + rb * 2 + 1]       = l0;
        g_ml[mb + (rb + 8) * 2]     = mx1;
        g_ml[mb + (rb + 8) * 2 + 1] = l1;
    }
}

// ---------------- merge the two KV splits -> half g_attn ----------------
__global__ void attn_merge_kernel() {
    int idx = blockIdx.x * blockDim.x + threadIdx.x;
    const int total = 32 * NQT * 128 * 32;
    if (idx >= total) return;
    int lane = idx & 31;
    int row = idx >> 5;
    int r = row & 127;
    int bhqt = row >> 7;
    int qt = bhqt % NQT, bh = bhqt / NQT;
    int qr = qt * 128 + r;
    if (qr >= SQ) return;
    size_t mb0 = (size_t)bhqt * 256 + r * 2;
    size_t mb1 = (size_t)(32 * NQT + bhqt) * 256 + r * 2;
    float m0 = g_ml[mb0], la = g_ml[mb0 + 1];
    float m1 = g_ml[mb1], lb = g_ml[mb1 + 1];
    float m = fmaxf(m0, m1);
    float c0 = __expf(m0 - m), c1 = __expf(m1 - m);
    float inv = 1.0f / (la * c0 + lb * c1);
    float2 a = *(const float2*)(g_op + ((size_t)bhqt * 128 + r) * 64 + 2 * lane);
    float2 bv = *(const float2*)(g_op + ((size_t)(32 * NQT + bhqt) * 128 + r) * 64 + 2 * lane);
    int b = bh >> 4, h = bh & 15;
    *(half2*)(g_attn + ((size_t)(b * SQ + qr)) * CC + h * DD + 2 * lane) =
        __floats2half2_rn((a.x * c0 + bv.x * c1) * inv,
                          (a.y * c0 + bv.y * c1) * inv);
}

// ---------------- launch ----------------
extern "C" void kernel_launch(void* const* d_in, const int* in_sizes, int n_in,
                              void* d_out, int out_size) {
    const float* hid = (const float*)d_in[0];
    const float* enc = (const float*)d_in[1];
    const float* Wq  = (const float*)d_in[2];
    const float* Wk  = (const float*)d_in[3];
    const float* Wv  = (const float*)d_in[4];
    const float* Wo  = (const float*)d_in[5];
    const float* bo  = (const float*)d_in[6];
    const float* gq  = (const float*)d_in[7];
    const float* bq  = (const float*)d_in[8];
    const float* gk  = (const float*)d_in[9];
    const float* bk  = (const float*)d_in[10];
    const float* rc  = (const float*)d_in[11];
    const float* rs  = (const float*)d_in[12];
    const float* kc  = (const float*)d_in[13];
    const float* vc  = (const float*)d_in[14];
    const int*   tok = (const int*)d_in[15];
    float* out = (float*)d_out;

    cudaFuncSetAttribute(gemm_qkv_mma,
                         cudaFuncAttributeMaxDynamicSharedMemorySize, GEMM_SMEM);
    cudaFuncSetAttribute(gemm_out_mma,
                         cudaFuncAttributeMaxDynamicSharedMemorySize, GEMM_SMEM);
    cudaFuncSetAttribute(attn_mma_kernel,
                         cudaFuncAttributeMaxDynamicSharedMemorySize, ATTN_SMEM);

    prep_h_kernel<<<(MM * CC / 4 + 255) / 256, 256>>>(hid, enc);            // 1
    prep_wt_kernel<<<4096, 256>>>(Wq, Wk, Wv, Wo);                          // 2
    inv_init_kernel<<<(TOK_N + 255) / 256, 256>>>();                        // 3
    gemm_qkv_mma<<<dim3(N3C / 128, (MM + 127) / 128), 256, GEMM_SMEM>>>();  // 4 (profiled)
    inv_scatter_kernel<<<(NTOK_N + 255) / 256, 256>>>(tok);                 // 5
    norm_kernel<<<BB * SKV + BB * SQ, 512>>>(gq, bq, gk, bk, rc, rs,
                                             kc, vc, tok);                  // 6
    transpose_v_kernel<<<BB * HH * NKT, 256>>>();                           // 7
    attn_mma_kernel<<<dim3(BB * HH, NQT, 2), 256, ATTN_SMEM>>>();           // 8
    attn_merge_kernel<<<(32 * NQT * 128 * 32 + 255) / 256, 256>>>();        // 9
    gemm_out_mma<<<dim3(CC / 128, (MM + 127) / 128), 256, GEMM_SMEM>>>(bo, out); // 10
}

// round 10
// speedup vs baseline: 2.0124x; 1.1478x over previous
#include <cuda_runtime.h>
#include <cuda_fp16.h>
#include <math.h>

#define BB 2
#define HH 16
#define DD 64
#define CC 1024
#define TEXT_N 226
#define NTOK_N 1024
#define TOK_N 4096
#define SQ (TEXT_N + NTOK_N)   /* 1250 */
#define SKV (TEXT_N + TOK_N)   /* 4322 */
#define N3C (3*CC)             /* 3072 */
#define SQP 1280
#define SKVP 4352
#define NKT 68
#define KSPLIT 34
#define NQT 10
#define MM (BB * SQ)           /* 2500 */

// ---------------- scratch (zero-initialized at module load) ----------------
__device__ __half g_h     [MM * CC];              // A of QKV gemm (half)
__device__ __half g_wqkvT [N3C * CC];             // W^T rows n, k contiguous
__device__ __half g_woT   [CC * CC];              // Wo^T
__device__ float  g_qkv   [MM * N3C];             // QKV gemm out (fp32)
__device__ __half g_khead [BB * HH * SKVP * DD];  // K heads, natural [j][d]
__device__ __half g_vhead [BB * HH * SKVP * DD];  // V heads, natural [j][d]
__device__ __half g_qhead [BB * HH * SQP * DD];   // Q*0.125
__device__ __half g_attn  [MM * CC];              // attention out (half)
__device__ int    g_inv   [TOK_N];
__device__ float  g_ml    [2 * 32 * NQT * 128 * 2];
__device__ float  g_op    [2 * 32 * NQT * 128 * 64];

// ---------------- helpers ----------------
__device__ __forceinline__ unsigned h2u(half2 h) {
    union { half2 h; unsigned u; } cvt;
    cvt.h = h;
    return cvt.u;
}
__device__ __forceinline__ void mma16(float* c, const unsigned* a,
                                      unsigned b0, unsigned b1) {
    asm volatile(
        "mma.sync.aligned.m16n8k16.row.col.f32.f16.f16.f32 "
        "{%0,%1,%2,%3}, {%4,%5,%6,%7}, {%8,%9}, {%0,%1,%2,%3};"
        : "+f"(c[0]), "+f"(c[1]), "+f"(c[2]), "+f"(c[3])
        : "r"(a[0]), "r"(a[1]), "r"(a[2]), "r"(a[3]), "r"(b0), "r"(b1));
}
__device__ __forceinline__ void ldsm4(unsigned* r, const __half* p) {
    unsigned a = (unsigned)__cvta_generic_to_shared(p);
    asm volatile("ldmatrix.sync.aligned.m8n8.x4.shared.b16 {%0,%1,%2,%3}, [%4];"
                 : "=r"(r[0]), "=r"(r[1]), "=r"(r[2]), "=r"(r[3]) : "r"(a));
}
__device__ __forceinline__ void ldsm4t(unsigned* r, const __half* p) {
    unsigned a = (unsigned)__cvta_generic_to_shared(p);
    asm volatile("ldmatrix.sync.aligned.m8n8.x4.trans.shared.b16 {%0,%1,%2,%3}, [%4];"
                 : "=r"(r[0]), "=r"(r[1]), "=r"(r[2]), "=r"(r[3]) : "r"(a));
}
__device__ __forceinline__ void cp16(void* smem_dst, const void* gsrc) {
    unsigned sa = (unsigned)__cvta_generic_to_shared(smem_dst);
    asm volatile("cp.async.cg.shared.global [%0], [%1], 16;" :: "r"(sa), "l"(gsrc));
}
__device__ __forceinline__ void cp16z(void* smem_dst, const void* gsrc, bool pred) {
    unsigned sa = (unsigned)__cvta_generic_to_shared(smem_dst);
    int sz = pred ? 16 : 0;
    asm volatile("cp.async.cg.shared.global [%0], [%1], 16, %2;"
                 :: "r"(sa), "l"(gsrc), "r"(sz));
}
#define CP_COMMIT() asm volatile("cp.async.commit_group;")
#define CP_WAIT0()  asm volatile("cp.async.wait_group 0;")

// ---------------- inverse token map ----------------
__global__ void inv_init_kernel() {
    int i = blockIdx.x * blockDim.x + threadIdx.x;
    if (i < TOK_N) g_inv[i] = -1;
}
__global__ void inv_scatter_kernel(const int* __restrict__ tok) {
    int i = blockIdx.x * blockDim.x + threadIdx.x;
    if (i < NTOK_N) atomicMax(&g_inv[tok[i]], i);
}

// ---------------- prep: h -> half (natural layout) ----------------
__global__ void prep_h_kernel(const float* __restrict__ hid,
                              const float* __restrict__ enc) {
    int i = blockIdx.x * blockDim.x + threadIdx.x;
    const int tot = MM * CC / 4;
    if (i >= tot) return;
    int r = i / (CC / 4), c4 = (i % (CC / 4)) * 4;
    int b = r / SQ, s = r % SQ;
    const float* src = (s < TEXT_N)
        ? enc + ((size_t)b * TEXT_N + s) * CC + c4
        : hid + ((size_t)b * NTOK_N + (s - TEXT_N)) * CC + c4;
    float4 v = *(const float4*)src;
    __half* d = g_h + (size_t)r * CC + c4;
    *(  half2*)(d)     = __floats2half2_rn(v.x, v.y);
    *(  half2*)(d + 2) = __floats2half2_rn(v.z, v.w);
}

// ---------------- prep: tiled transpose of weights -> half [n][k] ----------------
__global__ __launch_bounds__(256) void prep_wt_kernel(const float* __restrict__ Wq,
                                                      const float* __restrict__ Wk,
                                                      const float* __restrict__ Wv,
                                                      const float* __restrict__ Wo) {
    __shared__ float ts[32][33];
    int bid = blockIdx.x;
    const float* W; __half* dst; int k0, nbase, ncol;
    if (bid < 3072) {
        int kt = bid / 96, nt = bid % 96;
        k0 = kt * 32;
        nbase = nt * 32;
        W = (nt < 32) ? Wq : (nt < 64) ? Wk : Wv;
        ncol = (nt % 32) * 32;
        dst = g_wqkvT;
    } else {
        int b2 = bid - 3072;
        int kt = b2 / 32, nt = b2 % 32;
        k0 = kt * 32;
        nbase = nt * 32;
        ncol = nt * 32;
        W = Wo;
        dst = g_woT;
    }
    int rr = threadIdx.x >> 5, c = threadIdx.x & 31;
#pragma unroll
    for (int it = 0; it < 4; it++)
        ts[rr + 8 * it][c] = W[(size_t)(k0 + rr + 8 * it) * CC + ncol + c];
    __syncthreads();
#pragma unroll
    for (int it = 0; it < 4; it++) {
        int n = nbase + rr + 8 * it;
        dst[(size_t)n * CC + k0 + c] = __float2half_rn(ts[c][rr + 8 * it]);
    }
}

// ---------------- GEMMs: fp16 mma + ldmatrix, 128x128 block, K-tile 32 ----------
#define ASTRH 40
#define GEMM_SMEM ((2*128*ASTRH + 2*128*ASTRH) * 2)   /* 40960 B */

__device__ __forceinline__ void gemm_body(const __half* gA, const __half* gB,
                                          int m0, int n0, float cacc[2][8][4],
                                          int lane, int wid) {
    extern __shared__ __half smg[];
    __half* As = smg;
    __half* Bs = smg + 2 * 128 * ASTRH;
    const int tid = threadIdx.x;
    const int wm = wid & 3, wn = wid >> 2;
    // ldmatrix lane-address components
    const int a_row = (lane & 15), a_k = (lane >> 4) << 3;
    const int b_row = ((lane >> 4) << 3) + (lane & 7), b_k = ((lane >> 3) & 1) << 3;

    auto stage = [&](int kk, int st) {
        __half* dA = As + st * 128 * ASTRH;
        __half* dB = Bs + st * 128 * ASTRH;
#pragma unroll
        for (int i = tid; i < 1024; i += 256) {
            if (i < 512) {
                int r = i >> 2, c8 = (i & 3) * 8;
                cp16z(dA + r * ASTRH + c8,
                      gA + (size_t)(m0 + r) * CC + kk + c8, (m0 + r) < MM);
            } else {
                int j = i - 512;
                int r = j >> 2, c8 = (j & 3) * 8;
                cp16(dB + r * ASTRH + c8,
                     gB + (size_t)(n0 + r) * CC + kk + c8);
            }
        }
    };

    stage(0, 0);
    CP_COMMIT();

    for (int t = 0; t < 32; t++) {
        int st = t & 1;
        CP_WAIT0();
        __syncthreads();
        if (t + 1 < 32) { stage((t + 1) * 32, st ^ 1); CP_COMMIT(); }
        __half* pA = As + st * 128 * ASTRH;
        __half* pB = Bs + st * 128 * ASTRH;
#pragma unroll
        for (int ks = 0; ks < 2; ks++) {
            const int k0 = ks * 16;
            unsigned af[2][4];
            ldsm4(af[0], pA + (wm * 32 + a_row) * ASTRH + k0 + a_k);
            ldsm4(af[1], pA + (wm * 32 + 16 + a_row) * ASTRH + k0 + a_k);
#pragma unroll
            for (int nfp = 0; nfp < 4; nfp++) {
                unsigned bf[4];
                ldsm4(bf, pB + (wn * 64 + nfp * 16 + b_row) * ASTRH + k0 + b_k);
                mma16(cacc[0][2*nfp],   af[0], bf[0], bf[1]);
                mma16(cacc[0][2*nfp+1], af[0], bf[2], bf[3]);
                mma16(cacc[1][2*nfp],   af[1], bf[0], bf[1]);
                mma16(cacc[1][2*nfp+1], af[1], bf[2], bf[3]);
            }
        }
    }
}

__global__ __launch_bounds__(256, 2) void gemm_qkv_mma() {
    const int lane = threadIdx.x & 31, wid = threadIdx.x >> 5;
    const int g = lane >> 2, tig = lane & 3;
    const int wm = wid & 3, wn = wid >> 2;
    const int m0 = blockIdx.y * 128, n0 = blockIdx.x * 128;
    float cacc[2][8][4];
#pragma unroll
    for (int i = 0; i < 2; i++)
#pragma unroll
        for (int j = 0; j < 8; j++)
#pragma unroll
            for (int v = 0; v < 4; v++) cacc[i][j][v] = 0.f;
    gemm_body(g_h, g_wqkvT, m0, n0, cacc, lane, wid);
#pragma unroll
    for (int mf = 0; mf < 2; mf++) {
        int r0 = m0 + wm * 32 + mf * 16 + g;
#pragma unroll
        for (int nf = 0; nf < 8; nf++) {
            int col = n0 + wn * 64 + nf * 8 + 2 * tig;
            if (r0 < MM)
                *(float2*)(g_qkv + (size_t)r0 * N3C + col) =
                    make_float2(cacc[mf][nf][0], cacc[mf][nf][1]);
            if (r0 + 8 < MM)
                *(float2*)(g_qkv + (size_t)(r0 + 8) * N3C + col) =
                    make_float2(cacc[mf][nf][2], cacc[mf][nf][3]);
        }
    }
}

__global__ __launch_bounds__(256, 2) void gemm_out_mma(const float* __restrict__ bo,
                                                       float* __restrict__ out) {
    const int lane = threadIdx.x & 31, wid = threadIdx.x >> 5;
    const int g = lane >> 2, tig = lane & 3;
    const int wm = wid & 3, wn = wid >> 2;
    const int m0 = blockIdx.y * 128, n0 = blockIdx.x * 128;
    float cacc[2][8][4];
#pragma unroll
    for (int i = 0; i < 2; i++)
#pragma unroll
        for (int j = 0; j < 8; j++)
#pragma unroll
            for (int v = 0; v < 4; v++) cacc[i][j][v] = 0.f;
    gemm_body(g_attn, g_woT, m0, n0, cacc, lane, wid);
#pragma unroll
    for (int mf = 0; mf < 2; mf++) {
#pragma unroll
        for (int half_ = 0; half_ < 2; half_++) {
            int row = m0 + wm * 32 + mf * 16 + g + half_ * 8;
            if (row >= MM) continue;
            int b = row / SQ, s = row % SQ;
            size_t off = (s >= TEXT_N)
                ? ((size_t)(b * NTOK_N + (s - TEXT_N))) * CC
                : (size_t)BB * NTOK_N * CC + ((size_t)(b * TEXT_N + s)) * CC;
#pragma unroll
            for (int nf = 0; nf < 8; nf++) {
                int col = n0 + wn * 64 + nf * 8 + 2 * tig;
                float2 t = make_float2(cacc[mf][nf][0 + 2*half_] + bo[col],
                                       cacc[mf][nf][1 + 2*half_] + bo[col + 1]);
                *(float2*)(out + off + col) = t;
            }
        }
    }
}

// ---------------- combined norm: Q + KV, half outputs ----------------
__global__ __launch_bounds__(512) void norm_kernel(const float* __restrict__ gq,
                                                   const float* __restrict__ bq,
                                                   const float* __restrict__ gk,
                                                   const float* __restrict__ bk,
                                                   const float* __restrict__ rc,
                                                   const float* __restrict__ rs,
                                                   const float* __restrict__ kc,
                                                   const float* __restrict__ vc,
                                                   const int* __restrict__ tok) {
    const int bid = blockIdx.x;
    const int w = threadIdx.x >> 5;
    const int lid = threadIdx.x & 31;

    if (bid < BB * SKV) {
        const int b = bid / SKV, p = bid % SKV;
        const float* ksrc; const float* vsrc;
        if (p < TEXT_N) {
            size_t row = ((size_t)(b * SQ + p)) * N3C;
            ksrc = g_qkv + row + CC; vsrc = g_qkv + row + 2*CC;
        } else {
            int i = g_inv[p - TEXT_N];
            if (i >= 0) {
                size_t row = ((size_t)(b * SQ + TEXT_N + i)) * N3C;
                ksrc = g_qkv + row + CC; vsrc = g_qkv + row + 2*CC;
            } else {
                size_t row = ((size_t)(b * SKV + p)) * CC;
                ksrc = kc + row; vsrc = vc + row;
            }
        }
        float2 x = *(const float2*)(ksrc + w * DD + 2 * lid);
        float sum = x.x + x.y;
        float sq  = x.x * x.x + x.y * x.y;
#pragma unroll
        for (int off = 16; off; off >>= 1) {
            sum += __shfl_xor_sync(0xffffffffu, sum, off);
            sq  += __shfl_xor_sync(0xffffffffu, sq,  off);
        }
        float mean = sum * (1.0f / 64.0f);
        float var  = sq * (1.0f / 64.0f) - mean * mean;
        float rsig = rsqrtf(var + 1e-6f);
        float y0 = (x.x - mean) * rsig * gk[2*lid]   + bk[2*lid];
        float y1 = (x.y - mean) * rsig * gk[2*lid+1] + bk[2*lid+1];
        float o0 = y0, o1 = y1;
        if (p >= TEXT_N) {
            int rp = p - TEXT_N;
            float2 c  = *(const float2*)(rc + (size_t)rp * DD + 2 * lid);
            float2 sn = *(const float2*)(rs + (size_t)rp * DD + 2 * lid);
            o0 = y0 * c.x - y1 * sn.x;
            o1 = y1 * c.y + y0 * sn.y;
        }
        int bh = b * HH + w;
        size_t ob = ((size_t)bh * SKVP + p) * DD + 2 * lid;
        *(half2*)(g_khead + ob) = __floats2half2_rn(o0, o1);
        float2 v = *(const float2*)(vsrc + w * DD + 2 * lid);
        *(half2*)(g_vhead + ob) = __floats2half2_rn(v.x, v.y);
    } else {
        const int bs = bid - BB * SKV;
        const int b = bs / SQ, s = bs % SQ;
        size_t base = (size_t)bs * N3C + w * DD + 2 * lid;
        float2 x = *(const float2*)(g_qkv + base);
        float sum = x.x + x.y;
        float sq  = x.x * x.x + x.y * x.y;
#pragma unroll
        for (int off = 16; off; off >>= 1) {
            sum += __shfl_xor_sync(0xffffffffu, sum, off);
            sq  += __shfl_xor_sync(0xffffffffu, sq,  off);
        }
        float mean = sum * (1.0f / 64.0f);
        float var  = sq * (1.0f / 64.0f) - mean * mean;
        float rsig = rsqrtf(var + 1e-6f);
        float y0 = (x.x - mean) * rsig * gq[2*lid]   + bq[2*lid];
        float y1 = (x.y - mean) * rsig * gq[2*lid+1] + bq[2*lid+1];
        float o0 = y0, o1 = y1;
        if (s >= TEXT_N) {
            int rp = tok[s - TEXT_N];
            float2 c  = *(const float2*)(rc + (size_t)rp * DD + 2 * lid);
            float2 sn = *(const float2*)(rs + (size_t)rp * DD + 2 * lid);
            o0 = y0 * c.x - y1 * sn.x;
            o1 = y1 * c.y + y0 * sn.y;
        }
        *(half2*)(g_qhead + ((size_t)(b * HH + w) * SQP + s) * DD + 2 * lid) =
            __floats2half2_rn(o0 * 0.125f, o1 * 0.125f);
    }
}

// ---------------- flash attention: fp16 mma + ldmatrix, natural V ----------------
#define KSTR 72
#define KBUF (64 * KSTR)
#define QSOFF (4 * KBUF)
#define ATTN_SMEM ((QSOFF + 128 * KSTR) * 2)   /* 55296 B */

__global__ __launch_bounds__(256, 2) void attn_mma_kernel() {
    extern __shared__ __half sm16[];
    __half* Qs = sm16 + QSOFF;

    const int bh = blockIdx.x;
    const int qt = blockIdx.y;
    const int split = blockIdx.z;
    const int q0 = qt * 128;
    const int tid = threadIdx.x;
    const int w = tid >> 5, lane = tid & 31;
    const int g = lane >> 2, tig = lane & 3;
    const int rb = w * 16 + g;
    // ldmatrix lane-address components
    const int a_row = (lane & 15), a_k = (lane >> 4) << 3;               // A (Q)
    const int b_row = ((lane >> 4) << 3) + (lane & 7), b_k = ((lane >> 3) & 1) << 3;  // B (K)
    const int v_row = (((lane >> 3) & 1) << 3) + (lane & 7), v_c = ((lane >> 4) & 1) << 3; // B trans (V)

    const __half* kbase = g_khead + (size_t)bh * SKVP * DD;
    const __half* vbase = g_vhead + (size_t)bh * SKVP * DD;
    const __half* qbase = g_qhead + ((size_t)bh * SQP + q0) * DD;

    const int t0 = split * KSPLIT, t1 = t0 + KSPLIT;

    auto stage_kv = [&](__half* dst, int t) {
#pragma unroll
        for (int i = tid; i < 1024; i += 256) {
            if (i < 512) {
                int j = i >> 3, c8 = (i & 7) * 8;
                cp16(dst + j * KSTR + c8, kbase + (size_t)(t * 64 + j) * DD + c8);
            } else {
                int i2 = i - 512;
                int j = i2 >> 3, c8 = (i2 & 7) * 8;
                cp16(dst + KBUF + j * KSTR + c8,
                     vbase + (size_t)(t * 64 + j) * DD + c8);
            }
        }
    };

    // stage Q + first KV tile
#pragma unroll
    for (int i = tid; i < 1024; i += 256) {
        int r = i >> 3, c8 = (i & 7) * 8;
        cp16(Qs + r * KSTR + c8, qbase + r * DD + c8);
    }
    stage_kv(sm16, t0);
    CP_COMMIT();
    CP_WAIT0();
    __syncthreads();

    unsigned qf[4][4];
#pragma unroll
    for (int ks = 0; ks < 4; ks++)
        ldsm4(qf[ks], Qs + (w * 16 + a_row) * KSTR + 16 * ks + a_k);

    float oacc[8][4];
#pragma unroll
    for (int nf = 0; nf < 8; nf++)
#pragma unroll
        for (int v = 0; v < 4; v++) oacc[nf][v] = 0.f;
    float mx0 = -1e30f, mx1 = -1e30f, l0 = 0.f, l1 = 0.f;

    if (t0 + 1 < t1) { stage_kv(sm16 + 2 * KBUF, t0 + 1); CP_COMMIT(); }

    for (int t = t0; t < t1; t++) {
        int st = (t - t0) & 1;
        __half* Ks = sm16 + st * (2 * KBUF);
        __half* Vs = Ks + KBUF;
        const int kt = t * 64;

        // S = Q K^T
        float sacc[8][4];
#pragma unroll
        for (int nf = 0; nf < 8; nf++)
#pragma unroll
            for (int v = 0; v < 4; v++) sacc[nf][v] = 0.f;
#pragma unroll
        for (int ks = 0; ks < 4; ks++) {
            const int k0 = 16 * ks;
#pragma unroll
            for (int nfp = 0; nfp < 4; nfp++) {
                unsigned bf[4];
                ldsm4(bf, Ks + (nfp * 16 + b_row) * KSTR + k0 + b_k);
                mma16(sacc[2*nfp],   qf[ks], bf[0], bf[1]);
                mma16(sacc[2*nfp+1], qf[ks], bf[2], bf[3]);
            }
        }

        // mask tail columns
        if (kt + 64 > SKV) {
#pragma unroll
            for (int nf = 0; nf < 8; nf++) {
                int c = kt + nf * 8 + 2 * tig;
                if (c >= SKV)     { sacc[nf][0] = -1e30f; sacc[nf][2] = -1e30f; }
                if (c + 1 >= SKV) { sacc[nf][1] = -1e30f; sacc[nf][3] = -1e30f; }
            }
        }

        // online softmax (rows rb, rb+8); write p back into sacc
        float tmax0 = -1e30f, tmax1 = -1e30f;
#pragma unroll
        for (int nf = 0; nf < 8; nf++) {
            tmax0 = fmaxf(tmax0, fmaxf(sacc[nf][0], sacc[nf][1]));
            tmax1 = fmaxf(tmax1, fmaxf(sacc[nf][2], sacc[nf][3]));
        }
        tmax0 = fmaxf(tmax0, __shfl_xor_sync(0xffffffffu, tmax0, 1));
        tmax0 = fmaxf(tmax0, __shfl_xor_sync(0xffffffffu, tmax0, 2));
        tmax1 = fmaxf(tmax1, __shfl_xor_sync(0xffffffffu, tmax1, 1));
        tmax1 = fmaxf(tmax1, __shfl_xor_sync(0xffffffffu, tmax1, 2));
        float mn0 = fmaxf(mx0, tmax0), mn1 = fmaxf(mx1, tmax1);
        float corr0 = __expf(mx0 - mn0), corr1 = __expf(mx1 - mn1);
        mx0 = mn0; mx1 = mn1;

        float tsum0 = 0.f, tsum1 = 0.f;
#pragma unroll
        for (int nf = 0; nf < 8; nf++) {
            sacc[nf][0] = __expf(sacc[nf][0] - mn0);
            sacc[nf][1] = __expf(sacc[nf][1] - mn0);
            sacc[nf][2] = __expf(sacc[nf][2] - mn1);
            sacc[nf][3] = __expf(sacc[nf][3] - mn1);
            tsum0 += sacc[nf][0] + sacc[nf][1];
            tsum1 += sacc[nf][2] + sacc[nf][3];
        }
        tsum0 += __shfl_xor_sync(0xffffffffu, tsum0, 1);
        tsum0 += __shfl_xor_sync(0xffffffffu, tsum0, 2);
        tsum1 += __shfl_xor_sync(0xffffffffu, tsum1, 1);
        tsum1 += __shfl_xor_sync(0xffffffffu, tsum1, 2);
        l0 = l0 * corr0 + tsum0;
        l1 = l1 * corr1 + tsum1;
#pragma unroll
        for (int nf = 0; nf < 8; nf++) {
            oacc[nf][0] *= corr0; oacc[nf][1] *= corr0;
            oacc[nf][2] *= corr1; oacc[nf][3] *= corr1;
        }

        // O += P V   (P from registers; V B-frags via ldmatrix.trans on natural layout)
#pragma unroll
        for (int ks = 0; ks < 4; ks++) {
            unsigned pf[4];
            pf[0] = h2u(__floats2half2_rn(sacc[2*ks][0],   sacc[2*ks][1]));
            pf[1] = h2u(__floats2half2_rn(sacc[2*ks][2],   sacc[2*ks][3]));
            pf[2] = h2u(__floats2half2_rn(sacc[2*ks+1][0], sacc[2*ks+1][1]));
            pf[3] = h2u(__floats2half2_rn(sacc[2*ks+1][2], sacc[2*ks+1][3]));
#pragma unroll
            for (int nfp = 0; nfp < 4; nfp++) {
                unsigned vf[4];
                ldsm4t(vf, Vs + (16 * ks + v_row) * KSTR + nfp * 16 + v_c);
                mma16(oacc[2*nfp],   pf, vf[0], vf[1]);
                mma16(oacc[2*nfp+1], pf, vf[2], vf[3]);
            }
        }

        // pipeline: wait next tile's data, then stage tile t+2 into this buffer
        if (t + 1 < t1) {
            CP_WAIT0();
            __syncthreads();
            if (t + 2 < t1) { stage_kv(sm16 + st * (2 * KBUF), t + 2); CP_COMMIT(); }
        }
    }

    // split epilogue: unnormalized O + (m, l)
    const int bhqt = bh * NQT + qt;
    const size_t obase = ((size_t)(split * 32 * NQT + bhqt)) * 128 * 64;
#pragma unroll
    for (int nf = 0; nf < 8; nf++) {
        int col = nf * 8 + 2 * tig;
        *(float2*)(g_op + obase + (size_t)rb * 64 + col) =
            make_float2(oacc[nf][0], oacc[nf][1]);
        *(float2*)(g_op + obase + (size_t)(rb + 8) * 64 + col) =
            make_float2(oacc[nf][2], oacc[nf][3]);
    }
    if (tig == 0) {
        size_t mb = ((size_t)(split * 32 * NQT + bhqt)) * 128 * 2;
        g_ml[mb + rb * 2]           = mx0;
        g_ml[mb + rb * 2 + 1]       = l0;
        g_ml[mb + (rb + 8) * 2]     = mx1;
        g_ml[mb + (rb + 8) * 2 + 1] = l1;
    }
}

// ---------------- merge the two KV splits -> half g_attn ----------------
__global__ void attn_merge_kernel() {
    int idx = blockIdx.x * blockDim.x + threadIdx.x;
    const int total = 32 * NQT * 128 * 32;
    if (idx >= total) return;
    int lane = idx & 31;
    int row = idx >> 5;
    int r = row & 127;
    int bhqt = row >> 7;
    int qt = bhqt % NQT, bh = bhqt / NQT;
    int qr = qt * 128 + r;
    if (qr >= SQ) return;
    size_t mb0 = (size_t)bhqt * 256 + r * 2;
    size_t mb1 = (size_t)(32 * NQT + bhqt) * 256 + r * 2;
    float m0 = g_ml[mb0], la = g_ml[mb0 + 1];
    float m1 = g_ml[mb1], lb = g_ml[mb1 + 1];
    float m = fmaxf(m0, m1);
    float c0 = __expf(m0 - m), c1 = __expf(m1 - m);
    float inv = 1.0f / (la * c0 + lb * c1);
    float2 a = *(const float2*)(g_op + ((size_t)bhqt * 128 + r) * 64 + 2 * lane);
    float2 bv = *(const float2*)(g_op + ((size_t)(32 * NQT + bhqt) * 128 + r) * 64 + 2 * lane);
    int b = bh >> 4, h = bh & 15;
    *(half2*)(g_attn + ((size_t)(b * SQ + qr)) * CC + h * DD + 2 * lane) =
        __floats2half2_rn((a.x * c0 + bv.x * c1) * inv,
                          (a.y * c0 + bv.y * c1) * inv);
}

// ---------------- launch ----------------
extern "C" void kernel_launch(void* const* d_in, const int* in_sizes, int n_in,
                              void* d_out, int out_size) {
    const float* hid = (const float*)d_in[0];
    const float* enc = (const float*)d_in[1];
    const float* Wq  = (const float*)d_in[2];
    const float* Wk  = (const float*)d_in[3];
    const float* Wv  = (const float*)d_in[4];
    const float* Wo  = (const float*)d_in[5];
    const float* bo  = (const float*)d_in[6];
    const float* gq  = (const float*)d_in[7];
    const float* bq  = (const float*)d_in[8];
    const float* gk  = (const float*)d_in[9];
    const float* bk  = (const float*)d_in[10];
    const float* rc  = (const float*)d_in[11];
    const float* rs  = (const float*)d_in[12];
    const float* kc  = (const float*)d_in[13];
    const float* vc  = (const float*)d_in[14];
    const int*   tok = (const int*)d_in[15];
    float* out = (float*)d_out;

    cudaFuncSetAttribute(gemm_qkv_mma,
                         cudaFuncAttributeMaxDynamicSharedMemorySize, GEMM_SMEM);
    cudaFuncSetAttribute(gemm_out_mma,
                         cudaFuncAttributeMaxDynamicSharedMemorySize, GEMM_SMEM);
    cudaFuncSetAttribute(attn_mma_kernel,
                         cudaFuncAttributeMaxDynamicSharedMemorySize, ATTN_SMEM);

    prep_h_kernel<<<(MM * CC / 4 + 255) / 256, 256>>>(hid, enc);            // 1
    prep_wt_kernel<<<4096, 256>>>(Wq, Wk, Wv, Wo);                          // 2
    inv_init_kernel<<<(TOK_N + 255) / 256, 256>>>();                        // 3
    gemm_qkv_mma<<<dim3(N3C / 128, (MM + 127) / 128), 256, GEMM_SMEM>>>();  // 4 (profiled)
    inv_scatter_kernel<<<(NTOK_N + 255) / 256, 256>>>(tok);                 // 5
    norm_kernel<<<BB * SKV + BB * SQ, 512>>>(gq, bq, gk, bk, rc, rs,
                                             kc, vc, tok);                  // 6
    attn_mma_kernel<<<dim3(BB * HH, NQT, 2), 256, ATTN_SMEM>>>();           // 7
    attn_merge_kernel<<<(32 * NQT * 128 * 32 + 255) / 256, 256>>>();        // 8
    gemm_out_mma<<<dim3(CC / 128, (MM + 127) / 128), 256, GEMM_SMEM>>>(bo, out); // 9
}